// round 1
// baseline (speedup 1.0000x reference)
#include <cuda_runtime.h>
#include <cuda_bf16.h>
#include <math.h>

#define BATCH 8
#define DIM 96
#define HH 192
#define WW 192
#define NEXP 6
#define TOPK 3

// ---------- device scratch (no allocations allowed) ----------
__device__ float g_pooled[BATCH * DIM];
__device__ int   g_idx[BATCH * TOPK];
__device__ float g_w[BATCH * TOPK];

// ---------------------------------------------------------------
// Kernel A: per-(b,c) max+mean pooling over HxW
// grid = 768 blocks, 256 threads
// ---------------------------------------------------------------
__global__ __launch_bounds__(256) void pool_kernel(const float* __restrict__ x) {
    int bc = blockIdx.x;
    const float4* p4 = reinterpret_cast<const float4*>(x + (size_t)bc * (HH * WW));
    float mx = -1e30f, sm = 0.f;
    for (int i = threadIdx.x; i < (HH * WW / 4); i += 256) {
        float4 v = p4[i];
        mx = fmaxf(mx, fmaxf(fmaxf(v.x, v.y), fmaxf(v.z, v.w)));
        sm += (v.x + v.y) + (v.z + v.w);
    }
#pragma unroll
    for (int o = 16; o; o >>= 1) {
        mx = fmaxf(mx, __shfl_xor_sync(0xffffffffu, mx, o));
        sm += __shfl_xor_sync(0xffffffffu, sm, o);
    }
    __shared__ float smx[8], ssm[8];
    int w = threadIdx.x >> 5, l = threadIdx.x & 31;
    if (l == 0) { smx[w] = mx; ssm[w] = sm; }
    __syncthreads();
    if (threadIdx.x == 0) {
        float M = smx[0], S = ssm[0];
#pragma unroll
        for (int i = 1; i < 8; i++) { M = fmaxf(M, smx[i]); S += ssm[i]; }
        g_pooled[bc] = M + S * (1.0f / (HH * WW));
    }
}

// ---------------------------------------------------------------
// Kernel B: gate — noisy top-k routing. 1 block, 8 threads (1/batch)
// ---------------------------------------------------------------
__global__ void gate_kernel(const float* __restrict__ w_fc0,
                            const float* __restrict__ b_fc0,
                            const float* __restrict__ w_fc1,
                            const float* __restrict__ b_fc1) {
    int b = threadIdx.x;
    if (b >= BATCH) return;
    const float* p = g_pooled + b * DIM;
    float g[NEXP], nz[NEXP];
#pragma unroll
    for (int e = 0; e < NEXP; e++) {
        float d0 = b_fc0[e], d1 = b_fc1[e];
        for (int c = 0; c < DIM; c++) {
            float pv = p[c];
            d0 = fmaf(pv, w_fc0[e * DIM + c], d0);
            d1 = fmaf(pv, w_fc1[e * DIM + c], d1);
        }
        g[e]  = (d1 >= 0.f) ? d1 : 0.2f * d1;                       // leaky_relu 0.2
        nz[e] = fmaxf(d0, 0.f) + log1pf(expf(-fabsf(d0)));          // stable softplus
    }
    float mu = 0.f;
#pragma unroll
    for (int e = 0; e < NEXP; e++) mu += nz[e];
    mu *= (1.0f / NEXP);
    float var = 0.f;
#pragma unroll
    for (int e = 0; e < NEXP; e++) { float d = nz[e] - mu; var += d * d; }
    float sd = sqrtf(var / (NEXP - 1));                             // ddof=1
    float sc[NEXP];
#pragma unroll
    for (int e = 0; e < NEXP; e++) sc[e] = g[e] + (nz[e] - mu) / sd;

    // top-3 by score (ties -> lowest index, matching lax.top_k)
    bool used[NEXP] = {false, false, false, false, false, false};
    int idx[TOPK];
#pragma unroll
    for (int k = 0; k < TOPK; k++) {
        float best = -1e30f; int bi = 0;
#pragma unroll
        for (int e = 0; e < NEXP; e++)
            if (!used[e] && sc[e] > best) { best = sc[e]; bi = e; }
        used[bi] = true;
        idx[k] = bi;
    }
    // softmax over selected g
    float m = g[idx[0]];
    m = fmaxf(m, g[idx[1]]); m = fmaxf(m, g[idx[2]]);
    float ex[TOPK], s = 0.f;
#pragma unroll
    for (int k = 0; k < TOPK; k++) { ex[k] = expf(g[idx[k]] - m); s += ex[k]; }
    float inv = 1.0f / s;
#pragma unroll
    for (int k = 0; k < TOPK; k++) {
        g_idx[b * TOPK + k] = idx[k];
        g_w[b * TOPK + k]   = ex[k] * inv;
    }
}

// ---------------------------------------------------------------
// Kernel C: fused conv1 -> relu -> conv2 -> weighted sum over top-3 experts
// grid = (12 row-tiles, 96 channels, 8 batches), 192 threads (1 per w column)
// ---------------------------------------------------------------
__global__ __launch_bounds__(192) void moe_kernel(
    const float* __restrict__ x,
    const float* __restrict__ ew1, const float* __restrict__ eb1,
    const float* __restrict__ ew2, const float* __restrict__ eb2,
    float* __restrict__ out)
{
    const int t = threadIdx.x;              // 0..191, output column
    const int h0 = blockIdx.x * 16;         // tile start row
    const int c = blockIdx.y;
    const int b = blockIdx.z;

    // input tile with 2-halo: rows h0-2..h0+17 (20), cols -2..193 (196)
    __shared__ float in_s[20][196];
    // relu(conv1) tile with 1-halo: rows h0-1..h0+16 (18), cols -1..192 (194)
    __shared__ float c1_s[18][194];

    const float* xp = x + (size_t)(b * DIM + c) * (HH * WW);
    for (int idx = t; idx < 20 * 196; idx += 192) {
        int ri = idx / 196, ji = idx - ri * 196;
        int h = h0 - 2 + ri, w = ji - 2;
        float v = 0.f;
        if ((unsigned)h < (unsigned)HH && (unsigned)w < (unsigned)WW)
            v = xp[h * WW + w];
        in_s[ri][ji] = v;
    }

    float acc[16];
#pragma unroll
    for (int r = 0; r < 16; r++) acc[r] = 0.f;
    __syncthreads();

    for (int ki = 0; ki < TOPK; ki++) {
        const int   e   = g_idx[b * TOPK + ki];
        const float cof = g_w[b * TOPK + ki];
        const float* w1 = ew1 + ((size_t)e * DIM + c) * 9;
        const float* w2 = ew2 + ((size_t)e * DIM + c) * 9;
        const float k0 = w1[0], k1 = w1[1], k2 = w1[2];
        const float k3 = w1[3], k4 = w1[4], k5 = w1[5];
        const float k6 = w1[6], k7 = w1[7], k8 = w1[8];
        const float bias1 = eb1[e * DIM + c];

        // ---- conv1 + relu into c1_s (zero outside the valid image domain:
        //      conv2's zero padding applies to the conv1 OUTPUT) ----
        for (int jj = t; jj < 194; jj += 192) {
            const int wc = jj - 1;
            const bool wok = (unsigned)wc < (unsigned)WW;
            float a0 = in_s[0][jj], a1 = in_s[0][jj + 1], a2 = in_s[0][jj + 2];
            float b0 = in_s[1][jj], b1v = in_s[1][jj + 1], b2v = in_s[1][jj + 2];
#pragma unroll
            for (int r = 0; r < 18; r++) {
                float c0 = in_s[r + 2][jj], c1v = in_s[r + 2][jj + 1], c2v = in_s[r + 2][jj + 2];
                float v = fmaf(k0, a0, fmaf(k1, a1, fmaf(k2, a2,
                          fmaf(k3, b0, fmaf(k4, b1v, fmaf(k5, b2v,
                          fmaf(k6, c0, fmaf(k7, c1v, fmaf(k8, c2v, bias1)))))))));
                const int hr = h0 + r - 1;
                const bool hok = (unsigned)hr < (unsigned)HH;
                c1_s[r][jj] = (wok && hok) ? fmaxf(v, 0.f) : 0.f;
                a0 = b0; a1 = b1v; a2 = b2v;
                b0 = c0; b1v = c1v; b2v = c2v;
            }
        }
        __syncthreads();

        // ---- conv2 (weights pre-scaled by gate coeff) accumulate ----
        const float s0 = cof * w2[0], s1 = cof * w2[1], s2 = cof * w2[2];
        const float s3 = cof * w2[3], s4 = cof * w2[4], s5 = cof * w2[5];
        const float s6 = cof * w2[6], s7 = cof * w2[7], s8 = cof * w2[8];
        const float bb = cof * eb2[e * DIM + c];
        {
            float a0 = c1_s[0][t], a1 = c1_s[0][t + 1], a2 = c1_s[0][t + 2];
            float b0 = c1_s[1][t], b1v = c1_s[1][t + 1], b2v = c1_s[1][t + 2];
#pragma unroll
            for (int r = 0; r < 16; r++) {
                float c0 = c1_s[r + 2][t], c1v = c1_s[r + 2][t + 1], c2v = c1_s[r + 2][t + 2];
                acc[r] += fmaf(s0, a0, fmaf(s1, a1, fmaf(s2, a2,
                          fmaf(s3, b0, fmaf(s4, b1v, fmaf(s5, b2v,
                          fmaf(s6, c0, fmaf(s7, c1v, fmaf(s8, c2v, bb)))))))));
                a0 = b0; a1 = b1v; a2 = b2v;
                b0 = c0; b1v = c1v; b2v = c2v;
            }
        }
        __syncthreads();
    }

    float* op = out + (size_t)(b * DIM + c) * (HH * WW) + h0 * WW + t;
#pragma unroll
    for (int r = 0; r < 16; r++) op[r * WW] = acc[r];
}

// ---------------------------------------------------------------
extern "C" void kernel_launch(void* const* d_in, const int* in_sizes, int n_in,
                              void* d_out, int out_size) {
    const float* x     = (const float*)d_in[0];
    const float* w_fc0 = (const float*)d_in[1];
    const float* b_fc0 = (const float*)d_in[2];
    const float* w_fc1 = (const float*)d_in[3];
    const float* b_fc1 = (const float*)d_in[4];
    const float* ew1   = (const float*)d_in[5];
    const float* eb1   = (const float*)d_in[6];
    const float* ew2   = (const float*)d_in[7];
    const float* eb2   = (const float*)d_in[8];
    float* out = (float*)d_out;

    pool_kernel<<<BATCH * DIM, 256>>>(x);
    gate_kernel<<<1, 32>>>(w_fc0, b_fc0, w_fc1, b_fc1);
    dim3 grid(HH / 16, DIM, BATCH);
    moe_kernel<<<grid, 192>>>(x, ew1, eb1, ew2, eb2, out);
}

// round 2
// speedup vs baseline: 1.3045x; 1.3045x over previous
#include <cuda_runtime.h>
#include <cuda_bf16.h>
#include <math.h>

#define BATCH 8
#define DIM 96
#define HH 192
#define WW 192
#define NEXP 6
#define TOPK 3

typedef unsigned long long u64;

// ---------- packed f32x2 helpers (sm_103a) ----------
__device__ __forceinline__ u64 pk2(float lo, float hi) {
    u64 d; asm("mov.b64 %0, {%1, %2};" : "=l"(d) : "f"(lo), "f"(hi)); return d;
}
__device__ __forceinline__ void upk2(u64 d, float& lo, float& hi) {
    asm("mov.b64 {%0, %1}, %2;" : "=f"(lo), "=f"(hi) : "l"(d));
}
__device__ __forceinline__ u64 fma2(u64 a, u64 b, u64 c) {
    u64 d; asm("fma.rn.f32x2 %0, %1, %2, %3;" : "=l"(d) : "l"(a), "l"(b), "l"(c)); return d;
}
__device__ __forceinline__ u64 add2(u64 a, u64 b) {
    u64 d; asm("add.rn.f32x2 %0, %1, %2;" : "=l"(d) : "l"(a), "l"(b)); return d;
}

// ---------- device scratch ----------
__device__ float g_pooled[BATCH * DIM];
__device__ int   g_idx[BATCH * TOPK];
__device__ float g_w[BATCH * TOPK];

// ---------------------------------------------------------------
// Kernel A: per-(b,c) max+mean pooling over HxW (dual accumulators)
// ---------------------------------------------------------------
__global__ __launch_bounds__(256) void pool_kernel(const float* __restrict__ x) {
    int bc = blockIdx.x;
    const float4* p4 = reinterpret_cast<const float4*>(x + (size_t)bc * (HH * WW));
    float mxa = -1e30f, mxb = -1e30f, sma = 0.f, smb = 0.f;
    // 9216 float4 total; step 512 with two loads => 18 exact iterations
    for (int i = threadIdx.x; i < (HH * WW / 4); i += 512) {
        float4 v = p4[i];
        float4 u = p4[i + 256];
        mxa = fmaxf(mxa, fmaxf(fmaxf(v.x, v.y), fmaxf(v.z, v.w)));
        sma += (v.x + v.y) + (v.z + v.w);
        mxb = fmaxf(mxb, fmaxf(fmaxf(u.x, u.y), fmaxf(u.z, u.w)));
        smb += (u.x + u.y) + (u.z + u.w);
    }
    float mx = fmaxf(mxa, mxb), sm = sma + smb;
#pragma unroll
    for (int o = 16; o; o >>= 1) {
        mx = fmaxf(mx, __shfl_xor_sync(0xffffffffu, mx, o));
        sm += __shfl_xor_sync(0xffffffffu, sm, o);
    }
    __shared__ float smx[8], ssm[8];
    int w = threadIdx.x >> 5, l = threadIdx.x & 31;
    if (l == 0) { smx[w] = mx; ssm[w] = sm; }
    __syncthreads();
    if (threadIdx.x == 0) {
        float M = smx[0], S = ssm[0];
#pragma unroll
        for (int i = 1; i < 8; i++) { M = fmaxf(M, smx[i]); S += ssm[i]; }
        g_pooled[bc] = M + S * (1.0f / (HH * WW));
    }
}

// ---------------------------------------------------------------
// Kernel B: gate — phase 1: one thread per (b,e) dot product;
//                  phase 2: one thread per batch scores/top-k.
// ---------------------------------------------------------------
__global__ __launch_bounds__(64) void gate_kernel(const float* __restrict__ w_fc0,
                                                  const float* __restrict__ b_fc0,
                                                  const float* __restrict__ w_fc1,
                                                  const float* __restrict__ b_fc1) {
    __shared__ float sh_g[BATCH][NEXP], sh_nz[BATCH][NEXP];
    int t = threadIdx.x;
    if (t < BATCH * NEXP) {
        int b = t / NEXP, e = t - b * NEXP;
        const float* p = g_pooled + b * DIM;
        float d0 = b_fc0[e], d1 = b_fc1[e];
        for (int c = 0; c < DIM; c++) {
            float pv = p[c];
            d0 = fmaf(pv, w_fc0[e * DIM + c], d0);
            d1 = fmaf(pv, w_fc1[e * DIM + c], d1);
        }
        sh_g[b][e]  = (d1 >= 0.f) ? d1 : 0.2f * d1;                  // leaky_relu 0.2
        sh_nz[b][e] = fmaxf(d0, 0.f) + log1pf(expf(-fabsf(d0)));     // stable softplus
    }
    __syncthreads();
    if (t < BATCH) {
        int b = t;
        float g[NEXP], nz[NEXP];
#pragma unroll
        for (int e = 0; e < NEXP; e++) { g[e] = sh_g[b][e]; nz[e] = sh_nz[b][e]; }
        float mu = 0.f;
#pragma unroll
        for (int e = 0; e < NEXP; e++) mu += nz[e];
        mu *= (1.0f / NEXP);
        float var = 0.f;
#pragma unroll
        for (int e = 0; e < NEXP; e++) { float d = nz[e] - mu; var += d * d; }
        float sd = sqrtf(var / (NEXP - 1));
        float sc[NEXP];
#pragma unroll
        for (int e = 0; e < NEXP; e++) sc[e] = g[e] + (nz[e] - mu) / sd;

        bool used[NEXP] = {false, false, false, false, false, false};
        int idx[TOPK];
#pragma unroll
        for (int k = 0; k < TOPK; k++) {
            float best = -1e30f; int bi = 0;
#pragma unroll
            for (int e = 0; e < NEXP; e++)
                if (!used[e] && sc[e] > best) { best = sc[e]; bi = e; }
            used[bi] = true;
            idx[k] = bi;
        }
        float m = fmaxf(g[idx[0]], fmaxf(g[idx[1]], g[idx[2]]));
        float ex[TOPK], s = 0.f;
#pragma unroll
        for (int k = 0; k < TOPK; k++) { ex[k] = expf(g[idx[k]] - m); s += ex[k]; }
        float inv = 1.0f / s;
#pragma unroll
        for (int k = 0; k < TOPK; k++) {
            g_idx[b * TOPK + k] = idx[k];
            g_w[b * TOPK + k]   = ex[k] * inv;
        }
    }
}

// ---------------------------------------------------------------
// Kernel C: fused conv1 -> relu -> conv2 -> weighted sum, packed f32x2.
// 96 threads, each owns output column pair (2t, 2t+1) for a 16-row tile.
// Shared layouts (+1 col shift) make every 3-tap window = two aligned
// float2 loads.
// ---------------------------------------------------------------
#define INW 196   // floats per row (cols -1..192 at idx 1..194 shifted; even stride)
#define INW2 98   // float2 per row

struct P3 { u64 p0, p1, p2; };

__device__ __forceinline__ P3 load3(const float2* row, int t) {
    float2 L = row[t];       // idx (2t, 2t+1)   = cols (2t-1, 2t)
    float2 R = row[t + 1];   // idx (2t+2, 2t+3) = cols (2t+1, 2t+2)
    P3 r;
    r.p0 = pk2(L.x, L.y);    // taps at cols (2t-1, 2t)
    r.p1 = pk2(L.y, R.x);    // taps at cols (2t,   2t+1)
    r.p2 = pk2(R.x, R.y);    // taps at cols (2t+1, 2t+2)
    return r;
}

__global__ __launch_bounds__(96) void moe_kernel(
    const float* __restrict__ x,
    const float* __restrict__ ew1, const float* __restrict__ eb1,
    const float* __restrict__ ew2, const float* __restrict__ eb2,
    float* __restrict__ out)
{
    const int t  = threadIdx.x;             // 0..95, column pair (2t, 2t+1)
    const int h0 = blockIdx.x * 16;
    const int c  = blockIdx.y;
    const int b  = blockIdx.z;

    // x tile: rows h0-2..h0+17 (20), cols -1..192 at idx 1..194 (x halo is 0 padding)
    __shared__ __align__(16) float in_s[20 * INW];
    // relu(conv1) tile: rows h0-1..h0+16 (18), cols -1..192 at idx 0..193
    __shared__ __align__(16) float c1_s[18 * INW];

    const float* xp = x + (size_t)(b * DIM + c) * (HH * WW);
    for (int idx = t; idx < 20 * INW; idx += 96) {
        int ri = idx / INW, ji = idx - ri * INW;
        int h = h0 - 2 + ri, w = ji - 1;
        float v = 0.f;
        if ((unsigned)h < (unsigned)HH && (unsigned)w < (unsigned)WW)
            v = xp[h * WW + w];
        in_s[idx] = v;
    }
    // c1 halo columns (-1 and 192) are always zero; conv1 never writes idx 0 / 193.
    if (t < 18) { c1_s[t * INW + 0] = 0.f; c1_s[t * INW + 193] = 0.f; }

    u64 acc[16];
#pragma unroll
    for (int r = 0; r < 16; r++) acc[r] = 0ull;
    __syncthreads();

    const float2* in2 = reinterpret_cast<const float2*>(in_s);
    const float2* c12 = reinterpret_cast<const float2*>(c1_s);

    for (int ki = 0; ki < TOPK; ki++) {
        const int   e   = g_idx[b * TOPK + ki];
        const float cof = g_w[b * TOPK + ki];
        const float* w1 = ew1 + ((size_t)e * DIM + c) * 9;
        const float* w2 = ew2 + ((size_t)e * DIM + c) * 9;

        // ---- conv1 + relu -> c1_s ----
        {
            u64 K0 = pk2(w1[0], w1[0]), K1 = pk2(w1[1], w1[1]), K2 = pk2(w1[2], w1[2]);
            u64 K3 = pk2(w1[3], w1[3]), K4 = pk2(w1[4], w1[4]), K5 = pk2(w1[5], w1[5]);
            u64 K6 = pk2(w1[6], w1[6]), K7 = pk2(w1[7], w1[7]), K8 = pk2(w1[8], w1[8]);
            float b1v = eb1[e * DIM + c];
            u64 B1 = pk2(b1v, b1v);

            P3 A = load3(in2 + 0 * INW2, t);
            P3 Brow = load3(in2 + 1 * INW2, t);
#pragma unroll
            for (int r = 0; r < 18; r++) {
                P3 C = load3(in2 + (r + 2) * INW2, t);
                u64 v = fma2(K0, A.p0, fma2(K1, A.p1, fma2(K2, A.p2,
                        fma2(K3, Brow.p0, fma2(K4, Brow.p1, fma2(K5, Brow.p2,
                        fma2(K6, C.p0, fma2(K7, C.p1, fma2(K8, C.p2, B1)))))))));
                float v0, v1; upk2(v, v0, v1);
                const int hr = h0 + r - 1;
                const bool hok = (unsigned)hr < (unsigned)HH;
                // conv2's zero padding lives in the conv1-output domain
                c1_s[r * INW + 2 * t + 1] = hok ? fmaxf(v0, 0.f) : 0.f;
                c1_s[r * INW + 2 * t + 2] = hok ? fmaxf(v1, 0.f) : 0.f;
                A = Brow; Brow = C;
            }
        }
        __syncthreads();

        // ---- conv2 (weights pre-scaled by gate coeff), accumulate ----
        {
            u64 S0 = pk2(cof * w2[0], cof * w2[0]), S1 = pk2(cof * w2[1], cof * w2[1]);
            u64 S2 = pk2(cof * w2[2], cof * w2[2]), S3 = pk2(cof * w2[3], cof * w2[3]);
            u64 S4 = pk2(cof * w2[4], cof * w2[4]), S5 = pk2(cof * w2[5], cof * w2[5]);
            u64 S6 = pk2(cof * w2[6], cof * w2[6]), S7 = pk2(cof * w2[7], cof * w2[7]);
            u64 S8 = pk2(cof * w2[8], cof * w2[8]);
            float bbv = cof * eb2[e * DIM + c];
            u64 BB = pk2(bbv, bbv);

            P3 A = load3(c12 + 0 * INW2, t);
            P3 Brow = load3(c12 + 1 * INW2, t);
#pragma unroll
            for (int r = 0; r < 16; r++) {
                P3 C = load3(c12 + (r + 2) * INW2, t);
                acc[r] = fma2(S0, A.p0, fma2(S1, A.p1, fma2(S2, A.p2,
                         fma2(S3, Brow.p0, fma2(S4, Brow.p1, fma2(S5, Brow.p2,
                         fma2(S6, C.p0, fma2(S7, C.p1, fma2(S8, C.p2,
                         add2(acc[r], BB))))))))));
                A = Brow; Brow = C;
            }
        }
        __syncthreads();
    }

    float* op = out + (size_t)(b * DIM + c) * (HH * WW) + h0 * WW + 2 * t;
#pragma unroll
    for (int r = 0; r < 16; r++) {
        float o0, o1; upk2(acc[r], o0, o1);
        reinterpret_cast<float2*>(op + r * WW)[0] = make_float2(o0, o1);
    }
}

// ---------------------------------------------------------------
extern "C" void kernel_launch(void* const* d_in, const int* in_sizes, int n_in,
                              void* d_out, int out_size) {
    const float* x     = (const float*)d_in[0];
    const float* w_fc0 = (const float*)d_in[1];
    const float* b_fc0 = (const float*)d_in[2];
    const float* w_fc1 = (const float*)d_in[3];
    const float* b_fc1 = (const float*)d_in[4];
    const float* ew1   = (const float*)d_in[5];
    const float* eb1   = (const float*)d_in[6];
    const float* ew2   = (const float*)d_in[7];
    const float* eb2   = (const float*)d_in[8];
    float* out = (float*)d_out;

    pool_kernel<<<BATCH * DIM, 256>>>(x);
    gate_kernel<<<1, 64>>>(w_fc0, b_fc0, w_fc1, b_fc1);
    dim3 grid(HH / 16, DIM, BATCH);
    moe_kernel<<<grid, 96>>>(x, ew1, eb1, ew2, eb2, out);
}